// round 4
// baseline (speedup 1.0000x reference)
#include <cuda_runtime.h>
#include <math.h>
#include <stdint.h>
#include <stddef.h>

#define NN 50000
#define EE 800000

// ---------------- scratch (static __device__, no allocation) ----------------
static __device__ int   g_is64;
static __device__ int   g_src[EE];
static __device__ int   g_dst[EE];
static __device__ int   g_deg[NN];
static __device__ int   g_off[NN + 1];
static __device__ int   g_cur[NN];
static __device__ int   g_eidx[EE];
static __device__ float g_efA[(size_t)EE * 64];
static __device__ float g_efB[(size_t)EE * 64];
static __device__ float g_se [(size_t)EE * 8];
static __device__ float g_xsp[(size_t)NN * 64];
static __device__ float g_xdp[(size_t)NN * 64];
static __device__ float g_xv [(size_t)NN * 128];
static __device__ float g_ss [NN * 8];
static __device__ float g_sd [NN * 8];
static __device__ float g_h1 [(size_t)NN * 256];
static __device__ float g_h2 [(size_t)NN * 256];
static __device__ float g_xg [(size_t)NN * 320];
static __device__ float g_wae[64 * 8];

__device__ __forceinline__ float elu1(float x) { return x > 0.f ? x : expm1f(x); }
__device__ __forceinline__ float lrelu(float x) { return x > 0.f ? x : 0.2f * x; }

// ---------------- dtype detection + index conversion + degree zero ----------------
// If edge_index is int64 (values < 2^31), every odd int32 slot (high word) is 0.
// If it is int32, odd slots are random src values in [0, NN) — all-zero over 4096
// samples has negligible probability. Reads stay within 8192 ints (< buffer size
// under either dtype).
__global__ void detect_kernel(const int* __restrict__ a32) {
    __shared__ int any_nz;
    if (threadIdx.x == 0) any_nz = 0;
    __syncthreads();
    int nz = 0;
    for (int i = threadIdx.x; i < 4096; i += blockDim.x)
        nz |= (a32[2 * i + 1] != 0);
    if (nz) atomicOr(&any_nz, 1);
    __syncthreads();
    if (threadIdx.x == 0) g_is64 = (any_nz == 0) ? 1 : 0;
}

__global__ void zero_deg_kernel() {
    int i = blockIdx.x * blockDim.x + threadIdx.x;
    if (i < NN) g_deg[i] = 0;
}

__global__ void conv_idx_kernel(const int* __restrict__ a32) {
    int i = blockIdx.x * blockDim.x + threadIdx.x;
    if (i < EE) {
        if (g_is64) {
            g_src[i] = a32[2 * (size_t)i];
            g_dst[i] = a32[2 * (size_t)EE + 2 * (size_t)i];
        } else {
            g_src[i] = a32[i];
            g_dst[i] = a32[(size_t)EE + i];
        }
    }
}

// ---------------- CSR build ----------------
__global__ void count_kernel() {
    int i = blockIdx.x * blockDim.x + threadIdx.x;
    if (i < EE) atomicAdd(&g_deg[g_dst[i]], 1);
}

__global__ void scan_kernel() {
    __shared__ int s[1024];
    __shared__ int carry_s;
    int tid = threadIdx.x;
    if (tid == 0) carry_s = 0;
    __syncthreads();
    for (int base = 0; base < NN; base += 1024) {
        int v = (base + tid < NN) ? g_deg[base + tid] : 0;
        s[tid] = v;
        __syncthreads();
        for (int d = 1; d < 1024; d <<= 1) {
            int t = (tid >= d) ? s[tid - d] : 0;
            __syncthreads();
            s[tid] += t;
            __syncthreads();
        }
        int incl = s[tid];
        int carry = carry_s;
        if (base + tid < NN) {
            int ex = carry + incl - v;
            g_off[base + tid] = ex;
            g_cur[base + tid] = ex;
        }
        __syncthreads();
        if (tid == 1023) carry_s = carry + incl;
        __syncthreads();
    }
    if (tid == 0) g_off[NN] = carry_s;
}

__global__ void scatter_kernel() {
    int i = blockIdx.x * blockDim.x + threadIdx.x;
    if (i < EE) {
        int d = g_dst[i];
        int p = atomicAdd(&g_cur[d], 1);
        g_eidx[p] = i;
    }
}

// ---------------- generic tiled GEMM (C = A @ W), optional edge-MLP epilogue --------
// mode 0: plain store. mode 1: C[r] = relu(acc + xsp[src[r]] + xdp[dst[r]] + bias), Cn==64, bn==0.
__global__ __launch_bounds__(256) void gemm_kernel(
        const float* __restrict__ A, const float* __restrict__ W,
        float* __restrict__ C, int M, int K, int Cn, int mode,
        const float* __restrict__ bias) {
    __shared__ float As[16][65];
    __shared__ float Ws[16][64];
    int tid = threadIdx.x;                 // 256
    int bm = blockIdx.x * 64;
    int bn = blockIdx.y * 64;
    int tm = (tid / 16) * 4;
    int tn = (tid % 16) * 4;
    int lm  = tid / 4;
    int lk4 = (tid % 4) * 4;
    int wk = tid / 16;
    int wn = (tid % 16) * 4;

    float acc[4][4];
#pragma unroll
    for (int i = 0; i < 4; i++)
#pragma unroll
        for (int j = 0; j < 4; j++) acc[i][j] = 0.f;

    for (int k0 = 0; k0 < K; k0 += 16) {
        float4 av = make_float4(0.f, 0.f, 0.f, 0.f);
        if (bm + lm < M) av = *(const float4*)&A[(size_t)(bm + lm) * K + k0 + lk4];
        As[lk4 + 0][lm] = av.x;
        As[lk4 + 1][lm] = av.y;
        As[lk4 + 2][lm] = av.z;
        As[lk4 + 3][lm] = av.w;
        float4 wv = *(const float4*)&W[(size_t)(k0 + wk) * Cn + bn + wn];
        *(float4*)&Ws[wk][wn] = wv;
        __syncthreads();
#pragma unroll
        for (int k = 0; k < 16; k++) {
            float a0 = As[k][tm], a1 = As[k][tm + 1], a2 = As[k][tm + 2], a3 = As[k][tm + 3];
            float b0 = Ws[k][tn], b1 = Ws[k][tn + 1], b2 = Ws[k][tn + 2], b3 = Ws[k][tn + 3];
            acc[0][0] = fmaf(a0, b0, acc[0][0]); acc[0][1] = fmaf(a0, b1, acc[0][1]);
            acc[0][2] = fmaf(a0, b2, acc[0][2]); acc[0][3] = fmaf(a0, b3, acc[0][3]);
            acc[1][0] = fmaf(a1, b0, acc[1][0]); acc[1][1] = fmaf(a1, b1, acc[1][1]);
            acc[1][2] = fmaf(a1, b2, acc[1][2]); acc[1][3] = fmaf(a1, b3, acc[1][3]);
            acc[2][0] = fmaf(a2, b0, acc[2][0]); acc[2][1] = fmaf(a2, b1, acc[2][1]);
            acc[2][2] = fmaf(a2, b2, acc[2][2]); acc[2][3] = fmaf(a2, b3, acc[2][3]);
            acc[3][0] = fmaf(a3, b0, acc[3][0]); acc[3][1] = fmaf(a3, b1, acc[3][1]);
            acc[3][2] = fmaf(a3, b2, acc[3][2]); acc[3][3] = fmaf(a3, b3, acc[3][3]);
        }
        __syncthreads();
    }

    if (mode == 0) {
#pragma unroll
        for (int i = 0; i < 4; i++) {
            int r = bm + tm + i;
            if (r < M) {
                float4 v = make_float4(acc[i][0], acc[i][1], acc[i][2], acc[i][3]);
                *(float4*)&C[(size_t)r * Cn + bn + tn] = v;
            }
        }
    } else {
        float4 bv = *(const float4*)&bias[tn];
#pragma unroll
        for (int i = 0; i < 4; i++) {
            int r = bm + tm + i;
            if (r < M) {
                int s = g_src[r], d = g_dst[r];
                float4 a = *(const float4*)&g_xsp[(size_t)s * 64 + tn];
                float4 b = *(const float4*)&g_xdp[(size_t)d * 64 + tn];
                float4 v;
                v.x = fmaxf(acc[i][0] + a.x + b.x + bv.x, 0.f);
                v.y = fmaxf(acc[i][1] + a.y + b.y + bv.y, 0.f);
                v.z = fmaxf(acc[i][2] + a.z + b.z + bv.z, 0.f);
                v.w = fmaxf(acc[i][3] + a.w + b.w + bv.w, 0.f);
                *(float4*)&C[(size_t)r * 64 + tn] = v;
            }
        }
    }
}

// ---------------- per-node attention scalars: ss[n,h], sd[n,h] ----------------
__global__ void node_scalar_kernel(const float* __restrict__ xv, const float* __restrict__ a_s,
                                   const float* __restrict__ a_d, int D) {
    int idx = blockIdx.x * blockDim.x + threadIdx.x;
    if (idx >= NN * 8) return;
    int node = idx >> 3, h = idx & 7;
    const float* xr = xv + (size_t)node * 8 * D + h * D;
    const float* as = a_s + h * D;
    const float* ad = a_d + h * D;
    float s1 = 0.f, s2 = 0.f;
    for (int d = 0; d < D; ++d) {
        float v = xr[d];
        s1 = fmaf(v, as[d], s1);
        s2 = fmaf(v, ad[d], s2);
    }
    g_ss[idx] = s1;
    g_sd[idx] = s2;
}

// ---------------- wae[k,h] = sum_d cWe[k, h*16+d] * a_e[h,d] ----------------
__global__ void wae_kernel(const float* __restrict__ cWe, const float* __restrict__ a_e) {
    int idx = threadIdx.x;   // 512
    int k = idx >> 3, h = idx & 7;
    const float* w = cWe + k * 128 + h * 16;
    const float* a = a_e + h * 16;
    float s = 0.f;
#pragma unroll
    for (int d = 0; d < 16; ++d) s = fmaf(w[d], a[d], s);
    g_wae[k * 8 + h] = s;
}

// ---------------- se[e,h] = e_feat[e] . wae[:,h] ----------------
__global__ __launch_bounds__(256) void se_kernel(const float* __restrict__ ef) {
    __shared__ float sef[32][65];
    __shared__ float swae[512];
    int tid = threadIdx.x;
    size_t e0 = (size_t)blockIdx.x * 32;
    for (int i = tid; i < 512; i += 256) swae[i] = g_wae[i];
    for (int i = tid; i < 512; i += 256) {
        int e = i >> 4, c = (i & 15) << 2;
        float4 v = *(const float4*)&ef[(e0 + e) * 64 + c];
        sef[e][c] = v.x; sef[e][c + 1] = v.y; sef[e][c + 2] = v.z; sef[e][c + 3] = v.w;
    }
    __syncthreads();
    int e = tid >> 3, h = tid & 7;
    float s = 0.f;
#pragma unroll
    for (int k = 0; k < 64; ++k) s = fmaf(sef[e][k], swae[k * 8 + h], s);
    g_se[(e0 + e) * 8 + h] = s;
}

// ---------------- EGAT per-dst-node kernel (warp per node, two passes) ----------
__global__ __launch_bounds__(256) void egat_node_kernel(
        const float* __restrict__ xv, const float* __restrict__ ef,
        const float* __restrict__ cWe, float* __restrict__ hout) {
    __shared__ float sef[8][64];
    int gwarp = (blockIdx.x * blockDim.x + threadIdx.x) >> 5;
    int lane = threadIdx.x & 31;
    int wslot = threadIdx.x >> 5;
    if (gwarp >= NN) return;
    int n = gwarp;
    int beg = g_off[n], end = g_off[n + 1];
    float* myef = sef[wslot];

    // pass 1: per-head max of logits. lane -> (edge offset lane>>3, head lane&7)
    int h1 = lane & 7;
    int eo = lane >> 3;
    float sd1 = g_sd[n * 8 + h1];
    float mx = -INFINITY;
    for (int i = beg; i < end; i += 4) {
        int ii = i + eo;
        float lg = -INFINITY;
        if (ii < end) {
            int e = g_eidx[ii];
            int s = g_src[e];
            lg = lrelu(g_ss[s * 8 + h1] + sd1 + g_se[(size_t)e * 8 + h1]);
        }
        mx = fmaxf(mx, lg);
    }
    mx = fmaxf(mx, __shfl_xor_sync(0xffffffffu, mx, 8));
    mx = fmaxf(mx, __shfl_xor_sync(0xffffffffu, mx, 16));

    // pass 2 layout: head h2 = lane>>2, dims (lane&3)
    int h2 = lane >> 2;
    float mxh = __shfl_sync(0xffffffffu, mx, h2);
    float sd2 = __shfl_sync(0xffffffffu, sd1, h2);

    float sumex = 0.f;
    float av0 = 0.f, av1 = 0.f, av2 = 0.f, av3 = 0.f;
    float accT[16];
#pragma unroll
    for (int i = 0; i < 16; i++) accT[i] = 0.f;
    int kbase = (lane & 3) << 4;

    for (int i = beg; i < end; ++i) {
        int e = g_eidx[i];
        int s = g_src[e];
        if (lane < 16) {
            float4 v = *(const float4*)&ef[(size_t)e * 64 + (lane << 2)];
            *(float4*)&myef[lane << 2] = v;
        }
        float v = lrelu(g_ss[s * 8 + h2] + sd2 + g_se[(size_t)e * 8 + h2]);
        float ex = __expf(v - mxh);
        sumex += ex;
        float4 xvv = *(const float4*)&xv[(size_t)s * 128 + (lane << 2)];
        __syncwarp();
        av0 = fmaf(ex, xvv.x, av0);
        av1 = fmaf(ex, xvv.y, av1);
        av2 = fmaf(ex, xvv.z, av2);
        av3 = fmaf(ex, xvv.w, av3);
#pragma unroll
        for (int kk = 0; kk < 16; kk += 4) {
            float4 ev = *(const float4*)&myef[kbase + kk];
            accT[kk]     = fmaf(ex, ev.x, accT[kk]);
            accT[kk + 1] = fmaf(ex, ev.y, accT[kk + 1]);
            accT[kk + 2] = fmaf(ex, ev.z, accT[kk + 2]);
            accT[kk + 3] = fmaf(ex, ev.w, accT[kk + 3]);
        }
        __syncwarp();
    }

    float inv = 1.f / (sumex + 1e-16f);

    // node-part output: dims lane*4 .. lane*4+3 of first 128 cols
    float4 ov;
    ov.x = elu1(av0 * inv); ov.y = elu1(av1 * inv);
    ov.z = elu1(av2 * inv); ov.w = elu1(av3 * inv);
    *(float4*)&hout[(size_t)n * 256 + (lane << 2)] = ov;

    // edge-part: ne[h2, d] = inv * sum_k accT[h2,k] * cWe[k, h2*16+d]
    float pd[16];
#pragma unroll
    for (int d = 0; d < 16; ++d) pd[d] = 0.f;
#pragma unroll
    for (int kk = 0; kk < 16; ++kk) {
        float t = accT[kk];
        const float* wr = &cWe[(size_t)(kbase + kk) * 128 + h2 * 16];
#pragma unroll
        for (int d = 0; d < 16; ++d) pd[d] = fmaf(t, wr[d], pd[d]);
    }
#pragma unroll
    for (int d = 0; d < 16; ++d) {
        pd[d] += __shfl_xor_sync(0xffffffffu, pd[d], 1);
        pd[d] += __shfl_xor_sync(0xffffffffu, pd[d], 2);
    }
    int sel = lane & 3;
    float o0, o1, o2, o3;
    if (sel == 0)      { o0 = pd[0];  o1 = pd[1];  o2 = pd[2];  o3 = pd[3]; }
    else if (sel == 1) { o0 = pd[4];  o1 = pd[5];  o2 = pd[6];  o3 = pd[7]; }
    else if (sel == 2) { o0 = pd[8];  o1 = pd[9];  o2 = pd[10]; o3 = pd[11]; }
    else               { o0 = pd[12]; o1 = pd[13]; o2 = pd[14]; o3 = pd[15]; }
    float4 on;
    on.x = elu1(o0 * inv); on.y = elu1(o1 * inv);
    on.z = elu1(o2 * inv); on.w = elu1(o3 * inv);
    *(float4*)&hout[(size_t)n * 256 + 128 + h2 * 16 + (sel << 2)] = on;
}

// ---------------- final GAT (concat=False -> mean over heads) ----------------
__global__ __launch_bounds__(256) void gat_node_kernel(
        const float* __restrict__ xg, const float* __restrict__ bias,
        float* __restrict__ out) {
    int gwarp = (blockIdx.x * blockDim.x + threadIdx.x) >> 5;
    int lane = threadIdx.x & 31;
    if (gwarp >= NN) return;
    int n = gwarp;
    int beg = g_off[n], end = g_off[n + 1];

    int h1 = lane & 7;
    int eo = lane >> 3;
    float sd1 = g_sd[n * 8 + h1];
    float mx = -INFINITY;
    for (int i = beg; i < end; i += 4) {
        int ii = i + eo;
        float lg = -INFINITY;
        if (ii < end) {
            int e = g_eidx[ii];
            int s = g_src[e];
            lg = lrelu(g_ss[s * 8 + h1] + sd1);
        }
        mx = fmaxf(mx, lg);
    }
    mx = fmaxf(mx, __shfl_xor_sync(0xffffffffu, mx, 8));
    mx = fmaxf(mx, __shfl_xor_sync(0xffffffffu, mx, 16));

    int h2 = lane >> 2;
    float mxh = __shfl_sync(0xffffffffu, mx, h2);
    float sd2 = __shfl_sync(0xffffffffu, sd1, h2);
    int c0 = (lane & 3) * 10;

    float acc[10];
#pragma unroll
    for (int j = 0; j < 10; j++) acc[j] = 0.f;
    float sumex = 0.f;

    for (int i = beg; i < end; ++i) {
        int e = g_eidx[i];
        int s = g_src[e];
        float v = lrelu(g_ss[s * 8 + h2] + sd2);
        float ex = __expf(v - mxh);
        sumex += ex;
        const float* xr = &xg[(size_t)s * 320 + h2 * 40 + c0];
#pragma unroll
        for (int j = 0; j < 10; j += 2) {
            float2 t = *(const float2*)&xr[j];
            acc[j]     = fmaf(ex, t.x, acc[j]);
            acc[j + 1] = fmaf(ex, t.y, acc[j + 1]);
        }
    }
    float inv = 1.f / (sumex + 1e-16f);
#pragma unroll
    for (int j = 0; j < 10; ++j) {
        float v = acc[j] * inv;
        v += __shfl_xor_sync(0xffffffffu, v, 4);
        v += __shfl_xor_sync(0xffffffffu, v, 8);
        v += __shfl_xor_sync(0xffffffffu, v, 16);
        acc[j] = v;
    }
    if (lane < 4) {
#pragma unroll
        for (int j = 0; j < 10; ++j)
            out[(size_t)n * 40 + lane * 10 + j] = acc[j] * 0.125f + bias[lane * 10 + j];
    }
}

// ---------------- host ----------------
static inline dim3 ggrid(int M, int Cn) { return dim3((unsigned)((M + 63) / 64), (unsigned)(Cn / 64)); }

extern "C" void kernel_launch(void* const* d_in, const int* in_sizes, int n_in,
                              void* d_out, int out_size) {
    (void)in_sizes; (void)n_in; (void)out_size;
    const float* x     = (const float*)d_in[0];
    const int*   ei32  = (const int*)d_in[1];   // dtype decided on device (int32 vs int64)
    const float* ea    = (const float*)d_in[2];
    const float* e1_Ws = (const float*)d_in[3];
    const float* e1_Wd = (const float*)d_in[4];
    const float* e1_We = (const float*)d_in[5];
    const float* e1_b  = (const float*)d_in[6];
    const float* c1_Wv = (const float*)d_in[7];
    const float* c1_We = (const float*)d_in[8];
    const float* c1_as = (const float*)d_in[9];
    const float* c1_ad = (const float*)d_in[10];
    const float* c1_ae = (const float*)d_in[11];
    const float* e2_Ws = (const float*)d_in[12];
    const float* e2_Wd = (const float*)d_in[13];
    const float* e2_We = (const float*)d_in[14];
    const float* e2_b  = (const float*)d_in[15];
    const float* c2_Wv = (const float*)d_in[16];
    const float* c2_We = (const float*)d_in[17];
    const float* c2_as = (const float*)d_in[18];
    const float* c2_ad = (const float*)d_in[19];
    const float* c2_ae = (const float*)d_in[20];
    const float* g_Wp  = (const float*)d_in[21];
    const float* g_asP = (const float*)d_in[22];
    const float* g_adP = (const float*)d_in[23];
    const float* g_bP  = (const float*)d_in[24];
    float* out = (float*)d_out;

    void *p_efA, *p_efB, *p_xsp, *p_xdp, *p_xv, *p_h1, *p_h2, *p_xg;
    cudaGetSymbolAddress(&p_efA, g_efA);
    cudaGetSymbolAddress(&p_efB, g_efB);
    cudaGetSymbolAddress(&p_xsp, g_xsp);
    cudaGetSymbolAddress(&p_xdp, g_xdp);
    cudaGetSymbolAddress(&p_xv,  g_xv);
    cudaGetSymbolAddress(&p_h1,  g_h1);
    cudaGetSymbolAddress(&p_h2,  g_h2);
    cudaGetSymbolAddress(&p_xg,  g_xg);
    float* efA = (float*)p_efA; float* efB = (float*)p_efB;
    float* xsp = (float*)p_xsp; float* xdp = (float*)p_xdp;
    float* xv  = (float*)p_xv;  float* h1  = (float*)p_h1;
    float* h2  = (float*)p_h2;  float* xg  = (float*)p_xg;

    // CSR by dst
    detect_kernel<<<1, 1024>>>(ei32);
    conv_idx_kernel<<<(EE + 255) / 256, 256>>>(ei32);
    zero_deg_kernel<<<(NN + 255) / 256, 256>>>();
    count_kernel<<<(EE + 255) / 256, 256>>>();
    scan_kernel<<<1, 1024>>>();
    scatter_kernel<<<(EE + 255) / 256, 256>>>();

    // ---- layer 1: edge MLP ----
    gemm_kernel<<<ggrid(NN, 64), 256>>>(x, e1_Ws, xsp, NN, 128, 64, 0, nullptr);
    gemm_kernel<<<ggrid(NN, 64), 256>>>(x, e1_Wd, xdp, NN, 128, 64, 0, nullptr);
    gemm_kernel<<<ggrid(EE, 64), 256>>>(ea, e1_We, efA, EE, 16, 64, 1, e1_b);

    // ---- EGAT 1 ----
    gemm_kernel<<<ggrid(NN, 128), 256>>>(x, c1_Wv, xv, NN, 128, 128, 0, nullptr);
    node_scalar_kernel<<<(NN * 8 + 255) / 256, 256>>>(xv, c1_as, c1_ad, 16);
    wae_kernel<<<1, 512>>>(c1_We, c1_ae);
    se_kernel<<<EE / 32, 256>>>(efA);
    egat_node_kernel<<<(NN + 7) / 8, 256>>>(xv, efA, c1_We, h1);

    // ---- layer 2: edge MLP ----
    gemm_kernel<<<ggrid(NN, 64), 256>>>(h1, e2_Ws, xsp, NN, 256, 64, 0, nullptr);
    gemm_kernel<<<ggrid(NN, 64), 256>>>(h1, e2_Wd, xdp, NN, 256, 64, 0, nullptr);
    gemm_kernel<<<ggrid(EE, 64), 256>>>(efA, e2_We, efB, EE, 64, 64, 1, e2_b);

    // ---- EGAT 2 ----
    gemm_kernel<<<ggrid(NN, 128), 256>>>(h1, c2_Wv, xv, NN, 256, 128, 0, nullptr);
    node_scalar_kernel<<<(NN * 8 + 255) / 256, 256>>>(xv, c2_as, c2_ad, 16);
    wae_kernel<<<1, 512>>>(c2_We, c2_ae);
    se_kernel<<<EE / 32, 256>>>(efB);
    egat_node_kernel<<<(NN + 7) / 8, 256>>>(xv, efB, c2_We, h2);

    // ---- final GAT (mean over heads) ----
    gemm_kernel<<<ggrid(NN, 320), 256>>>(h2, g_Wp, xg, NN, 256, 320, 0, nullptr);
    node_scalar_kernel<<<(NN * 8 + 255) / 256, 256>>>(xg, g_asP, g_adP, 40);
    gat_node_kernel<<<(NN + 7) / 8, 256>>>(xg, g_bP, out);
}

// round 5
// speedup vs baseline: 1.0325x; 1.0325x over previous
#include <cuda_runtime.h>
#include <math.h>
#include <stdint.h>
#include <stddef.h>

#define NN 50000
#define EE 800000

// ---------------- scratch (static __device__, no allocation) ----------------
static __device__ int   g_is64;
static __device__ int   g_src[EE];       // edge order
static __device__ int   g_dst[EE];       // edge order
static __device__ int   g_pos[EE];       // edge id -> CSR slot
static __device__ int   g_srcc[EE];      // CSR order
static __device__ int   g_dstc[EE];      // CSR order
static __device__ int   g_deg[NN];
static __device__ int   g_off[NN + 1];
static __device__ int   g_cur[NN];
static __device__ float g_efA[(size_t)EE * 64];   // CSR order
static __device__ float g_efB[(size_t)EE * 64];   // CSR order
static __device__ float g_xsp[(size_t)NN * 64];
static __device__ float g_xdp[(size_t)NN * 64];
static __device__ float g_xv [(size_t)NN * 128];
static __device__ float g_ss [NN * 8];
static __device__ float g_sd [NN * 8];
static __device__ float g_h1 [(size_t)NN * 256];
static __device__ float g_h2 [(size_t)NN * 256];
static __device__ float g_xg [(size_t)NN * 320];
static __device__ float g_wae[64 * 8];

__device__ __forceinline__ float elu1(float x) { return x > 0.f ? x : expm1f(x); }
__device__ __forceinline__ float lrelu(float x) { return x > 0.f ? x : 0.2f * x; }

// ---------------- dtype detection + index conversion + degree zero ----------------
__global__ void detect_kernel(const int* __restrict__ a32) {
    __shared__ int any_nz;
    if (threadIdx.x == 0) any_nz = 0;
    __syncthreads();
    int nz = 0;
    for (int i = threadIdx.x; i < 4096; i += blockDim.x)
        nz |= (a32[2 * i + 1] != 0);
    if (nz) atomicOr(&any_nz, 1);
    __syncthreads();
    if (threadIdx.x == 0) g_is64 = (any_nz == 0) ? 1 : 0;
}

__global__ void zero_deg_kernel() {
    int i = blockIdx.x * blockDim.x + threadIdx.x;
    if (i < NN) g_deg[i] = 0;
}

__global__ void conv_idx_kernel(const int* __restrict__ a32) {
    int i = blockIdx.x * blockDim.x + threadIdx.x;
    if (i < EE) {
        if (g_is64) {
            g_src[i] = a32[2 * (size_t)i];
            g_dst[i] = a32[2 * (size_t)EE + 2 * (size_t)i];
        } else {
            g_src[i] = a32[i];
            g_dst[i] = a32[(size_t)EE + i];
        }
    }
}

// ---------------- CSR build ----------------
__global__ void count_kernel() {
    int i = blockIdx.x * blockDim.x + threadIdx.x;
    if (i < EE) atomicAdd(&g_deg[g_dst[i]], 1);
}

__global__ void scan_kernel() {
    __shared__ int s[1024];
    __shared__ int carry_s;
    int tid = threadIdx.x;
    if (tid == 0) carry_s = 0;
    __syncthreads();
    for (int base = 0; base < NN; base += 1024) {
        int v = (base + tid < NN) ? g_deg[base + tid] : 0;
        s[tid] = v;
        __syncthreads();
        for (int d = 1; d < 1024; d <<= 1) {
            int t = (tid >= d) ? s[tid - d] : 0;
            __syncthreads();
            s[tid] += t;
            __syncthreads();
        }
        int incl = s[tid];
        int carry = carry_s;
        if (base + tid < NN) {
            int ex = carry + incl - v;
            g_off[base + tid] = ex;
            g_cur[base + tid] = ex;
        }
        __syncthreads();
        if (tid == 1023) carry_s = carry + incl;
        __syncthreads();
    }
    if (tid == 0) g_off[NN] = carry_s;
}

__global__ void scatter_kernel() {
    int i = blockIdx.x * blockDim.x + threadIdx.x;
    if (i < EE) {
        int d = g_dst[i];
        int p = atomicAdd(&g_cur[d], 1);
        g_pos[i]  = p;
        g_srcc[p] = g_src[i];
        g_dstc[p] = d;
    }
}

// ---------------- generic tiled GEMM (C = A @ W) ----------------
// mode 0: plain store.
// mode 1: edge MLP, rows are EDGE ids; out row = g_pos[r]; gathers g_src/g_dst.
// mode 2: edge MLP, rows are CSR slots; out row = r; gathers g_srcc/g_dstc.
__global__ __launch_bounds__(256) void gemm_kernel(
        const float* __restrict__ A, const float* __restrict__ W,
        float* __restrict__ C, int M, int K, int Cn, int mode,
        const float* __restrict__ bias) {
    __shared__ float As[16][65];
    __shared__ float Ws[16][64];
    int tid = threadIdx.x;                 // 256
    int bm = blockIdx.x * 64;
    int bn = blockIdx.y * 64;
    int tm = (tid / 16) * 4;
    int tn = (tid % 16) * 4;
    int lm  = tid / 4;
    int lk4 = (tid % 4) * 4;
    int wk = tid / 16;
    int wn = (tid % 16) * 4;

    float acc[4][4];
#pragma unroll
    for (int i = 0; i < 4; i++)
#pragma unroll
        for (int j = 0; j < 4; j++) acc[i][j] = 0.f;

    for (int k0 = 0; k0 < K; k0 += 16) {
        float4 av = make_float4(0.f, 0.f, 0.f, 0.f);
        if (bm + lm < M) av = *(const float4*)&A[(size_t)(bm + lm) * K + k0 + lk4];
        As[lk4 + 0][lm] = av.x;
        As[lk4 + 1][lm] = av.y;
        As[lk4 + 2][lm] = av.z;
        As[lk4 + 3][lm] = av.w;
        float4 wv = *(const float4*)&W[(size_t)(k0 + wk) * Cn + bn + wn];
        *(float4*)&Ws[wk][wn] = wv;
        __syncthreads();
#pragma unroll
        for (int k = 0; k < 16; k++) {
            float a0 = As[k][tm], a1 = As[k][tm + 1], a2 = As[k][tm + 2], a3 = As[k][tm + 3];
            float b0 = Ws[k][tn], b1 = Ws[k][tn + 1], b2 = Ws[k][tn + 2], b3 = Ws[k][tn + 3];
            acc[0][0] = fmaf(a0, b0, acc[0][0]); acc[0][1] = fmaf(a0, b1, acc[0][1]);
            acc[0][2] = fmaf(a0, b2, acc[0][2]); acc[0][3] = fmaf(a0, b3, acc[0][3]);
            acc[1][0] = fmaf(a1, b0, acc[1][0]); acc[1][1] = fmaf(a1, b1, acc[1][1]);
            acc[1][2] = fmaf(a1, b2, acc[1][2]); acc[1][3] = fmaf(a1, b3, acc[1][3]);
            acc[2][0] = fmaf(a2, b0, acc[2][0]); acc[2][1] = fmaf(a2, b1, acc[2][1]);
            acc[2][2] = fmaf(a2, b2, acc[2][2]); acc[2][3] = fmaf(a2, b3, acc[2][3]);
            acc[3][0] = fmaf(a3, b0, acc[3][0]); acc[3][1] = fmaf(a3, b1, acc[3][1]);
            acc[3][2] = fmaf(a3, b2, acc[3][2]); acc[3][3] = fmaf(a3, b3, acc[3][3]);
        }
        __syncthreads();
    }

    if (mode == 0) {
#pragma unroll
        for (int i = 0; i < 4; i++) {
            int r = bm + tm + i;
            if (r < M) {
                float4 v = make_float4(acc[i][0], acc[i][1], acc[i][2], acc[i][3]);
                *(float4*)&C[(size_t)r * Cn + bn + tn] = v;
            }
        }
    } else {
        float4 bv = *(const float4*)&bias[tn];
#pragma unroll
        for (int i = 0; i < 4; i++) {
            int r = bm + tm + i;
            if (r < M) {
                int s, d, ro;
                if (mode == 1) { s = g_src[r];  d = g_dst[r];  ro = g_pos[r]; }
                else           { s = g_srcc[r]; d = g_dstc[r]; ro = r; }
                float4 a = *(const float4*)&g_xsp[(size_t)s * 64 + tn];
                float4 b = *(const float4*)&g_xdp[(size_t)d * 64 + tn];
                float4 v;
                v.x = fmaxf(acc[i][0] + a.x + b.x + bv.x, 0.f);
                v.y = fmaxf(acc[i][1] + a.y + b.y + bv.y, 0.f);
                v.z = fmaxf(acc[i][2] + a.z + b.z + bv.z, 0.f);
                v.w = fmaxf(acc[i][3] + a.w + b.w + bv.w, 0.f);
                *(float4*)&C[(size_t)ro * 64 + tn] = v;
            }
        }
    }
}

// ---------------- per-node attention scalars: ss[n,h], sd[n,h] ----------------
__global__ void node_scalar_kernel(const float* __restrict__ xv, const float* __restrict__ a_s,
                                   const float* __restrict__ a_d, int D) {
    int idx = blockIdx.x * blockDim.x + threadIdx.x;
    if (idx >= NN * 8) return;
    int node = idx >> 3, h = idx & 7;
    const float* xr = xv + (size_t)node * 8 * D + h * D;
    const float* as = a_s + h * D;
    const float* ad = a_d + h * D;
    float s1 = 0.f, s2 = 0.f;
    for (int d = 0; d < D; ++d) {
        float v = xr[d];
        s1 = fmaf(v, as[d], s1);
        s2 = fmaf(v, ad[d], s2);
    }
    g_ss[idx] = s1;
    g_sd[idx] = s2;
}

// ---------------- wae[k,h] = sum_d cWe[k, h*16+d] * a_e[h,d] ----------------
__global__ void wae_kernel(const float* __restrict__ cWe, const float* __restrict__ a_e) {
    int idx = threadIdx.x;   // 512
    int k = idx >> 3, h = idx & 7;
    const float* w = cWe + k * 128 + h * 16;
    const float* a = a_e + h * 16;
    float s = 0.f;
#pragma unroll
    for (int d = 0; d < 16; ++d) s = fmaf(w[d], a[d], s);
    g_wae[k * 8 + h] = s;
}

// ---------------- EGAT per-dst-node kernel (warp per node, single pass) --------
// ef is CSR-ordered: streaming reads. se computed inline from ef + preloaded wae.
// No max-subtraction: logits are O(1), fp32 exp is safe; softmax is shift-invariant.
__global__ __launch_bounds__(256) void egat_node_kernel(
        const float* __restrict__ xv, const float* __restrict__ efc,
        const float* __restrict__ cWe, float* __restrict__ hout) {
    int gwarp = (blockIdx.x * blockDim.x + threadIdx.x) >> 5;
    int lane = threadIdx.x & 31;
    if (gwarp >= NN) return;
    int n = gwarp;
    int beg = g_off[n], end = g_off[n + 1];

    int h2 = lane >> 2;            // head
    int kbase = (lane & 3) << 4;   // k-range [kbase, kbase+16)
    float sd2 = g_sd[n * 8 + h2];

    // preload wae[kbase+kk][h2]
    float wreg[16];
#pragma unroll
    for (int kk = 0; kk < 16; ++kk) wreg[kk] = g_wae[(kbase + kk) * 8 + h2];

    float sumex = 0.f;
    float av0 = 0.f, av1 = 0.f, av2 = 0.f, av3 = 0.f;
    float accT[16];
#pragma unroll
    for (int i = 0; i < 16; i++) accT[i] = 0.f;

#pragma unroll 2
    for (int i = beg; i < end; ++i) {
        int s = g_srcc[i];
        const float4* efr = (const float4*)&efc[(size_t)i * 64 + kbase];
        float4 e0 = efr[0], e1 = efr[1], e2 = efr[2], e3 = efr[3];
        // se partial over this lane's 16 k
        float se = e0.x * wreg[0];
        se = fmaf(e0.y, wreg[1], se);  se = fmaf(e0.z, wreg[2], se);  se = fmaf(e0.w, wreg[3], se);
        se = fmaf(e1.x, wreg[4], se);  se = fmaf(e1.y, wreg[5], se);  se = fmaf(e1.z, wreg[6], se);
        se = fmaf(e1.w, wreg[7], se);  se = fmaf(e2.x, wreg[8], se);  se = fmaf(e2.y, wreg[9], se);
        se = fmaf(e2.z, wreg[10], se); se = fmaf(e2.w, wreg[11], se); se = fmaf(e3.x, wreg[12], se);
        se = fmaf(e3.y, wreg[13], se); se = fmaf(e3.z, wreg[14], se); se = fmaf(e3.w, wreg[15], se);
        se += __shfl_xor_sync(0xffffffffu, se, 1);
        se += __shfl_xor_sync(0xffffffffu, se, 2);

        float lg = lrelu(g_ss[s * 8 + h2] + sd2 + se);
        float ex = __expf(lg);
        sumex += ex;

        float4 xvv = *(const float4*)&xv[(size_t)s * 128 + (lane << 2)];
        av0 = fmaf(ex, xvv.x, av0);
        av1 = fmaf(ex, xvv.y, av1);
        av2 = fmaf(ex, xvv.z, av2);
        av3 = fmaf(ex, xvv.w, av3);
        accT[0]  = fmaf(ex, e0.x, accT[0]);  accT[1]  = fmaf(ex, e0.y, accT[1]);
        accT[2]  = fmaf(ex, e0.z, accT[2]);  accT[3]  = fmaf(ex, e0.w, accT[3]);
        accT[4]  = fmaf(ex, e1.x, accT[4]);  accT[5]  = fmaf(ex, e1.y, accT[5]);
        accT[6]  = fmaf(ex, e1.z, accT[6]);  accT[7]  = fmaf(ex, e1.w, accT[7]);
        accT[8]  = fmaf(ex, e2.x, accT[8]);  accT[9]  = fmaf(ex, e2.y, accT[9]);
        accT[10] = fmaf(ex, e2.z, accT[10]); accT[11] = fmaf(ex, e2.w, accT[11]);
        accT[12] = fmaf(ex, e3.x, accT[12]); accT[13] = fmaf(ex, e3.y, accT[13]);
        accT[14] = fmaf(ex, e3.z, accT[14]); accT[15] = fmaf(ex, e3.w, accT[15]);
    }

    float inv = 1.f / (sumex + 1e-16f);

    // node-part output: dims lane*4 .. lane*4+3 of first 128 cols
    float4 ov;
    ov.x = elu1(av0 * inv); ov.y = elu1(av1 * inv);
    ov.z = elu1(av2 * inv); ov.w = elu1(av3 * inv);
    *(float4*)&hout[(size_t)n * 256 + (lane << 2)] = ov;

    // edge-part: ne[h2, d] = inv * sum_k accT[h2,k] * cWe[k, h2*16+d]
    float pd[16];
#pragma unroll
    for (int d = 0; d < 16; ++d) pd[d] = 0.f;
#pragma unroll
    for (int kk = 0; kk < 16; ++kk) {
        float t = accT[kk];
        const float* wr = &cWe[(size_t)(kbase + kk) * 128 + h2 * 16];
#pragma unroll
        for (int d = 0; d < 16; ++d) pd[d] = fmaf(t, wr[d], pd[d]);
    }
#pragma unroll
    for (int d = 0; d < 16; ++d) {
        pd[d] += __shfl_xor_sync(0xffffffffu, pd[d], 1);
        pd[d] += __shfl_xor_sync(0xffffffffu, pd[d], 2);
    }
    int sel = lane & 3;
    float o0, o1, o2, o3;
    if (sel == 0)      { o0 = pd[0];  o1 = pd[1];  o2 = pd[2];  o3 = pd[3]; }
    else if (sel == 1) { o0 = pd[4];  o1 = pd[5];  o2 = pd[6];  o3 = pd[7]; }
    else if (sel == 2) { o0 = pd[8];  o1 = pd[9];  o2 = pd[10]; o3 = pd[11]; }
    else               { o0 = pd[12]; o1 = pd[13]; o2 = pd[14]; o3 = pd[15]; }
    float4 on;
    on.x = elu1(o0 * inv); on.y = elu1(o1 * inv);
    on.z = elu1(o2 * inv); on.w = elu1(o3 * inv);
    *(float4*)&hout[(size_t)n * 256 + 128 + h2 * 16 + (sel << 2)] = on;
}

// ---------------- final GAT (concat=False -> mean over heads) ----------------
__global__ __launch_bounds__(256) void gat_node_kernel(
        const float* __restrict__ xg, const float* __restrict__ bias,
        float* __restrict__ out) {
    int gwarp = (blockIdx.x * blockDim.x + threadIdx.x) >> 5;
    int lane = threadIdx.x & 31;
    if (gwarp >= NN) return;
    int n = gwarp;
    int beg = g_off[n], end = g_off[n + 1];

    int h2 = lane >> 2;
    float sd2 = g_sd[n * 8 + h2];
    int c0 = (lane & 3) * 10;

    float acc[10];
#pragma unroll
    for (int j = 0; j < 10; j++) acc[j] = 0.f;
    float sumex = 0.f;

#pragma unroll 2
    for (int i = beg; i < end; ++i) {
        int s = g_srcc[i];
        float v = lrelu(g_ss[s * 8 + h2] + sd2);
        float ex = __expf(v);
        sumex += ex;
        const float* xr = &xg[(size_t)s * 320 + h2 * 40 + c0];
#pragma unroll
        for (int j = 0; j < 10; j += 2) {
            float2 t = *(const float2*)&xr[j];
            acc[j]     = fmaf(ex, t.x, acc[j]);
            acc[j + 1] = fmaf(ex, t.y, acc[j + 1]);
        }
    }
    float inv = 1.f / (sumex + 1e-16f);
#pragma unroll
    for (int j = 0; j < 10; ++j) {
        float v = acc[j] * inv;
        v += __shfl_xor_sync(0xffffffffu, v, 4);
        v += __shfl_xor_sync(0xffffffffu, v, 8);
        v += __shfl_xor_sync(0xffffffffu, v, 16);
        acc[j] = v;
    }
    if (lane < 4) {
#pragma unroll
        for (int j = 0; j < 10; ++j)
            out[(size_t)n * 40 + lane * 10 + j] = acc[j] * 0.125f + bias[lane * 10 + j];
    }
}

// ---------------- host ----------------
static inline dim3 ggrid(int M, int Cn) { return dim3((unsigned)((M + 63) / 64), (unsigned)(Cn / 64)); }

extern "C" void kernel_launch(void* const* d_in, const int* in_sizes, int n_in,
                              void* d_out, int out_size) {
    (void)in_sizes; (void)n_in; (void)out_size;
    const float* x     = (const float*)d_in[0];
    const int*   ei32  = (const int*)d_in[1];   // dtype decided on device (int32 vs int64)
    const float* ea    = (const float*)d_in[2];
    const float* e1_Ws = (const float*)d_in[3];
    const float* e1_Wd = (const float*)d_in[4];
    const float* e1_We = (const float*)d_in[5];
    const float* e1_b  = (const float*)d_in[6];
    const float* c1_Wv = (const float*)d_in[7];
    const float* c1_We = (const float*)d_in[8];
    const float* c1_as = (const float*)d_in[9];
    const float* c1_ad = (const float*)d_in[10];
    const float* c1_ae = (const float*)d_in[11];
    const float* e2_Ws = (const float*)d_in[12];
    const float* e2_Wd = (const float*)d_in[13];
    const float* e2_We = (const float*)d_in[14];
    const float* e2_b  = (const float*)d_in[15];
    const float* c2_Wv = (const float*)d_in[16];
    const float* c2_We = (const float*)d_in[17];
    const float* c2_as = (const float*)d_in[18];
    const float* c2_ad = (const float*)d_in[19];
    const float* c2_ae = (const float*)d_in[20];
    const float* g_Wp  = (const float*)d_in[21];
    const float* g_asP = (const float*)d_in[22];
    const float* g_adP = (const float*)d_in[23];
    const float* g_bP  = (const float*)d_in[24];
    float* out = (float*)d_out;

    void *p_efA, *p_efB, *p_xsp, *p_xdp, *p_xv, *p_h1, *p_h2, *p_xg;
    cudaGetSymbolAddress(&p_efA, g_efA);
    cudaGetSymbolAddress(&p_efB, g_efB);
    cudaGetSymbolAddress(&p_xsp, g_xsp);
    cudaGetSymbolAddress(&p_xdp, g_xdp);
    cudaGetSymbolAddress(&p_xv,  g_xv);
    cudaGetSymbolAddress(&p_h1,  g_h1);
    cudaGetSymbolAddress(&p_h2,  g_h2);
    cudaGetSymbolAddress(&p_xg,  g_xg);
    float* efA = (float*)p_efA; float* efB = (float*)p_efB;
    float* xsp = (float*)p_xsp; float* xdp = (float*)p_xdp;
    float* xv  = (float*)p_xv;  float* h1  = (float*)p_h1;
    float* h2  = (float*)p_h2;  float* xg  = (float*)p_xg;

    // CSR by dst
    detect_kernel<<<1, 1024>>>(ei32);
    conv_idx_kernel<<<(EE + 255) / 256, 256>>>(ei32);
    zero_deg_kernel<<<(NN + 255) / 256, 256>>>();
    count_kernel<<<(EE + 255) / 256, 256>>>();
    scan_kernel<<<1, 1024>>>();
    scatter_kernel<<<(EE + 255) / 256, 256>>>();

    // ---- layer 1: edge MLP (output CSR-permuted) ----
    gemm_kernel<<<ggrid(NN, 64), 256>>>(x, e1_Ws, xsp, NN, 128, 64, 0, nullptr);
    gemm_kernel<<<ggrid(NN, 64), 256>>>(x, e1_Wd, xdp, NN, 128, 64, 0, nullptr);
    gemm_kernel<<<ggrid(EE, 64), 256>>>(ea, e1_We, efA, EE, 16, 64, 1, e1_b);

    // ---- EGAT 1 ----
    gemm_kernel<<<ggrid(NN, 128), 256>>>(x, c1_Wv, xv, NN, 128, 128, 0, nullptr);
    node_scalar_kernel<<<(NN * 8 + 255) / 256, 256>>>(xv, c1_as, c1_ad, 16);
    wae_kernel<<<1, 512>>>(c1_We, c1_ae);
    egat_node_kernel<<<(NN + 7) / 8, 256>>>(xv, efA, c1_We, h1);

    // ---- layer 2: edge MLP (rows already CSR slots) ----
    gemm_kernel<<<ggrid(NN, 64), 256>>>(h1, e2_Ws, xsp, NN, 256, 64, 0, nullptr);
    gemm_kernel<<<ggrid(NN, 64), 256>>>(h1, e2_Wd, xdp, NN, 256, 64, 0, nullptr);
    gemm_kernel<<<ggrid(EE, 64), 256>>>(efA, e2_We, efB, EE, 64, 64, 2, e2_b);

    // ---- EGAT 2 ----
    gemm_kernel<<<ggrid(NN, 128), 256>>>(h1, c2_Wv, xv, NN, 256, 128, 0, nullptr);
    node_scalar_kernel<<<(NN * 8 + 255) / 256, 256>>>(xv, c2_as, c2_ad, 16);
    wae_kernel<<<1, 512>>>(c2_We, c2_ae);
    egat_node_kernel<<<(NN + 7) / 8, 256>>>(xv, efB, c2_We, h2);

    // ---- final GAT (mean over heads) ----
    gemm_kernel<<<ggrid(NN, 320), 256>>>(h2, g_Wp, xg, NN, 256, 320, 0, nullptr);
    node_scalar_kernel<<<(NN * 8 + 255) / 256, 256>>>(xg, g_asP, g_adP, 40);
    gat_node_kernel<<<(NN + 7) / 8, 256>>>(xg, g_bP, out);
}